// round 16
// baseline (speedup 1.0000x reference)
#include <cuda_runtime.h>
#include <cuda_bf16.h>
#include <cuda_fp16.h>
#include <mma.h>
#include <cstdint>

using namespace nvcuda;

#define B_SZ 8192
#define N_SZ 8192
#define D_SZ 1024
#define EPS_F 1e-6f
constexpr float INV_T = 1.0f / 0.92f;

// ---------------- scratch (device globals; no allocations allowed) ----------
__device__ __half g_qhat[(size_t)B_SZ * D_SZ]; // 16 MB (fp16 normalized q)
__device__ __half g_nhat[(size_t)N_SZ * D_SZ]; // 16 MB (fp16 normalized n)
__device__ float g_s1[B_SZ];
__device__ float g_S2[B_SZ];
__device__ float g_loss;

// ---------------------------------------------------------------------------
#define CP_ASYNC16(dst, src) \
    asm volatile("cp.async.cg.shared.global [%0], [%1], 16;" :: "r"(dst), "l"(src) : "memory")
#define CP_COMMIT() asm volatile("cp.async.commit_group;" ::: "memory")
#define CP_WAIT1()  asm volatile("cp.async.wait_group 1;" ::: "memory")
#define CP_WAIT0()  asm volatile("cp.async.wait_group 0;" ::: "memory")

__device__ __forceinline__ uint32_t smem_u32(const void* p) {
    uint32_t a;
    asm("{ .reg .u64 t; cvta.to.shared.u64 t, %1; cvt.u32.u64 %0, t; }"
        : "=r"(a) : "l"(p));
    return a;
}

// ---------------------------------------------------------------------------
// Kernel 1: prep q,p -> qhat (fp16), s1, zero S2
// ---------------------------------------------------------------------------
__global__ __launch_bounds__(256) void prep_qp_kernel(const float* __restrict__ q,
                                                      const float* __restrict__ p) {
    const int b = blockIdx.x;
    const int t = threadIdx.x;
    const float4* q4 = (const float4*)(q + (size_t)b * D_SZ);
    const float4* p4 = (const float4*)(p + (size_t)b * D_SZ);

    float4 a = q4[t];
    float4 c = p4[t];
    float qq = a.x * a.x + a.y * a.y + a.z * a.z + a.w * a.w;
    float pp = c.x * c.x + c.y * c.y + c.z * c.z + c.w * c.w;
    float qp = a.x * c.x + a.y * c.y + a.z * c.z + a.w * c.w;

    #pragma unroll
    for (int off = 16; off > 0; off >>= 1) {
        qq += __shfl_xor_sync(0xffffffff, qq, off);
        pp += __shfl_xor_sync(0xffffffff, pp, off);
        qp += __shfl_xor_sync(0xffffffff, qp, off);
    }
    __shared__ float sq[8], sp[8], sqp[8], s_rq;
    const int wid = t >> 5, lane = t & 31;
    if (lane == 0) { sq[wid] = qq; sp[wid] = pp; sqp[wid] = qp; }
    __syncthreads();
    if (t == 0) {
        float tq = 0.f, tp = 0.f, tqp = 0.f;
        #pragma unroll
        for (int i = 0; i < 8; i++) { tq += sq[i]; tp += sp[i]; tqp += sqp[i]; }
        float qn = sqrtf(tq), pn = sqrtf(tp);
        float pos = tqp / fmaxf(qn * pn, EPS_F);
        g_s1[b] = __expf(pos * INV_T);
        g_S2[b] = 0.0f;
        s_rq = (qn > 0.f) ? (1.0f / qn) : 0.0f;
    }
    __syncthreads();
    const float rq = s_rq;
    __half* out = g_qhat + (size_t)b * D_SZ + t * 4;
    out[0] = __float2half(a.x * rq);
    out[1] = __float2half(a.y * rq);
    out[2] = __float2half(a.z * rq);
    out[3] = __float2half(a.w * rq);
}

// ---------------------------------------------------------------------------
// Kernel 2: prep negatives -> nhat (fp16)
// ---------------------------------------------------------------------------
__global__ __launch_bounds__(256) void prep_n_kernel(const float* __restrict__ nkeys) {
    const int nrow = blockIdx.x;
    const int t = threadIdx.x;
    const float4* n4 = (const float4*)(nkeys + (size_t)nrow * D_SZ);
    float4 a = n4[t];
    float nn = a.x * a.x + a.y * a.y + a.z * a.z + a.w * a.w;
    #pragma unroll
    for (int off = 16; off > 0; off >>= 1) nn += __shfl_xor_sync(0xffffffff, nn, off);
    __shared__ float sn[8], s_rn;
    const int wid = t >> 5, lane = t & 31;
    if (lane == 0) sn[wid] = nn;
    __syncthreads();
    if (t == 0) {
        float tn = 0.f;
        #pragma unroll
        for (int i = 0; i < 8; i++) tn += sn[i];
        float norm = sqrtf(tn);
        s_rn = (norm > 0.f) ? (1.0f / norm) : 0.0f;
    }
    __syncthreads();
    const float rn = s_rn;
    __half* out = g_nhat + (size_t)nrow * D_SZ + t * 4;
    out[0] = __float2half(a.x * rn);
    out[1] = __float2half(a.y * rn);
    out[2] = __float2half(a.z * rn);
    out[3] = __float2half(a.w * rn);
}

// ---------------------------------------------------------------------------
// Kernel 3: zero loss; keeps GEMM at captured launch slot #4.
// ---------------------------------------------------------------------------
__global__ void init_loss_kernel() {
    if (threadIdx.x == 0) g_loss = 0.0f;
}

// ---------------------------------------------------------------------------
// Kernel 4: wmma GEMM (fp16 in, fp16 acc) + fused exp/rowsum.
//   Block 256x256, 256 threads (8 warps, 2x4), warp tile 128x64, KC=64,
//   2-stage cp.async, 1 CTA/SM (147KB smem). Proven R11 two-barrier
//   pipeline: prefetch -> commit -> wait1 -> sync -> compute -> sync.
//   25% less LDSM per MAC than the 128x256 config; half the CTA count.
// ---------------------------------------------------------------------------
#define BM 256
#define BN 256
#define KC 64
#define CHUNKS (D_SZ / KC)        // 16
#define KP 72                     // smem row pitch in fp16 elems (144B)
#define A_ST (BM * KP)            // 18432 elems
#define B_ST (BN * KP)            // 18432 elems
#define STAGE_ELEMS (A_ST + B_ST) // 36864 elems = 73728 B
#define SMEM_BYTES (2 * STAGE_ELEMS * 2)   // 147456
#define CPH 24                    // epilogue scratch pitch (halves)

__global__ __launch_bounds__(256, 1) void gemm_exp_kernel() {
    extern __shared__ __half sm[];
    const int tid = threadIdx.x;
    const int wid = tid >> 5, lane = tid & 31;
    const int wm = wid >> 2;          // 0..1 -> 128-row strip
    const int wn = wid & 3;           // 0..3 -> 64-col strip
    const int m0 = blockIdx.y * BM;
    const int n0 = blockIdx.x * BN;
    const uint32_t sbase = smem_u32(sm);

    // cp.async: 256 rows x 8 segs for A and for B -> 2048+2048 vecs,
    // 16 per thread.
    uint32_t a_off[8], b_off[8];
    const __half* a_src[8];
    const __half* b_src[8];
    #pragma unroll
    for (int i = 0; i < 8; i++) {
        int idx = tid + i * 256;
        int row = idx >> 3, seg = idx & 7;
        a_off[i] = (uint32_t)(row * KP + seg * 8) * 2;
        a_src[i] = g_qhat + (size_t)(m0 + row) * D_SZ + seg * 8;
        b_off[i] = (uint32_t)(A_ST + row * KP + seg * 8) * 2;
        b_src[i] = g_nhat + (size_t)(n0 + row) * D_SZ + seg * 8;
    }

    wmma::fragment<wmma::accumulator, 16, 16, 16, __half> acc[8][4];
    #pragma unroll
    for (int mf = 0; mf < 8; mf++)
        #pragma unroll
        for (int nf = 0; nf < 4; nf++)
            wmma::fill_fragment(acc[mf][nf], __float2half(0.0f));

    // Prologue: chunk 0 into slot 0
    {
        #pragma unroll
        for (int i = 0; i < 8; i++) {
            CP_ASYNC16(sbase + a_off[i], a_src[i]);
            CP_ASYNC16(sbase + b_off[i], b_src[i]);
        }
        CP_COMMIT();
    }

    for (int kt = 0; kt < CHUNKS; kt++) {
        if (kt + 1 < CHUNKS) {
            uint32_t st = sbase + ((kt + 1) & 1) * (STAGE_ELEMS * 2);
            int k0 = (kt + 1) * KC;
            #pragma unroll
            for (int i = 0; i < 8; i++) {
                CP_ASYNC16(st + a_off[i], a_src[i] + k0);
                CP_ASYNC16(st + b_off[i], b_src[i] + k0);
            }
            CP_COMMIT();
            CP_WAIT1();
        } else {
            CP_WAIT0();
        }
        __syncthreads();   // chunk kt visible to all warps

        const __half* As = sm + (kt & 1) * STAGE_ELEMS;
        const __half* Bs = As + A_ST;
        #pragma unroll
        for (int kk = 0; kk < 4; kk++) {
            wmma::fragment<wmma::matrix_a, 16, 16, 16, __half, wmma::row_major> af[8];
            #pragma unroll
            for (int mf = 0; mf < 8; mf++)
                wmma::load_matrix_sync(af[mf], As + (wm * 128 + mf * 16) * KP + kk * 16, KP);
            #pragma unroll
            for (int nf = 0; nf < 4; nf++) {
                wmma::fragment<wmma::matrix_b, 16, 16, 16, __half, wmma::col_major> bf;
                wmma::load_matrix_sync(bf, Bs + (wn * 64 + nf * 16) * KP + kk * 16, KP);
                #pragma unroll
                for (int mf = 0; mf < 8; mf++)
                    wmma::mma_sync(acc[mf][nf], af[mf], bf, acc[mf][nf]);
            }
        }
        __syncthreads();   // protect slot (kt&1) before refill at kt+2
    }

    // Epilogue: half accs -> scratch -> exp(fp32) -> rowsum.
    __half* scratch = sm + wid * (16 * CPH);
    #pragma unroll
    for (int mf = 0; mf < 8; mf++) {
        float partial = 0.0f;
        #pragma unroll
        for (int nf = 0; nf < 4; nf++) {
            wmma::store_matrix_sync(scratch, acc[mf][nf], CPH, wmma::mem_row_major);
            __syncwarp();
            const int r = lane & 15, h = lane >> 4;
            const __half* pr = scratch + r * CPH + h * 8;
            #pragma unroll
            for (int c = 0; c < 8; c++)
                partial += __expf(__half2float(pr[c]) * INV_T);
            __syncwarp();
        }
        partial += __shfl_xor_sync(0xffffffff, partial, 16);
        if (lane < 16)
            atomicAdd(&g_S2[m0 + wm * 128 + mf * 16 + lane], partial);
    }
}

// ---------------------------------------------------------------------------
// Kernel 5/6: per-row loss terms -> g_loss; write out.
// ---------------------------------------------------------------------------
__global__ __launch_bounds__(256) void finalize_partial_kernel() {
    const int b = blockIdx.x * 256 + threadIdx.x;
    float s1 = g_s1[b];
    float s2 = g_S2[b] * (1.0f / (float)N_SZ);
    float v = -logf(s1 / (s1 + s2));

    __shared__ float sd[256];
    sd[threadIdx.x] = v;
    __syncthreads();
    #pragma unroll
    for (int stride = 128; stride > 0; stride >>= 1) {
        if (threadIdx.x < stride) sd[threadIdx.x] += sd[threadIdx.x + stride];
        __syncthreads();
    }
    if (threadIdx.x == 0) atomicAdd(&g_loss, sd[0]);
}

__global__ void finalize_write_kernel(float* __restrict__ out) {
    out[0] = g_loss * (1.0f / (float)B_SZ);
}

// ---------------------------------------------------------------------------
extern "C" void kernel_launch(void* const* d_in, const int* in_sizes, int n_in,
                              void* d_out, int out_size) {
    const float* q  = (const float*)d_in[0];
    const float* p  = (const float*)d_in[1];
    const float* nk = (const float*)d_in[2];
    float* out = (float*)d_out;

    cudaFuncSetAttribute(gemm_exp_kernel,
                         cudaFuncAttributeMaxDynamicSharedMemorySize, SMEM_BYTES);

    prep_qp_kernel<<<B_SZ, 256>>>(q, p);
    prep_n_kernel<<<N_SZ, 256>>>(nk);
    init_loss_kernel<<<1, 32>>>();
    gemm_exp_kernel<<<dim3(N_SZ / BN, B_SZ / BM), 256, SMEM_BYTES>>>();
    finalize_partial_kernel<<<B_SZ / 256, 256>>>();
    finalize_write_kernel<<<1, 1>>>(out);
}

// round 17
// speedup vs baseline: 1.0474x; 1.0474x over previous
#include <cuda_runtime.h>
#include <cuda_bf16.h>
#include <cuda_fp16.h>
#include <mma.h>
#include <cstdint>

using namespace nvcuda;

#define B_SZ 8192
#define N_SZ 8192
#define D_SZ 1024
#define EPS_F 1e-6f
constexpr float INV_T = 1.0f / 0.92f;

// ---------------- scratch (device globals; no allocations allowed) ----------
__device__ __half g_qhat[(size_t)B_SZ * D_SZ]; // 16 MB (fp16 normalized q)
__device__ __half g_nhat[(size_t)N_SZ * D_SZ]; // 16 MB (fp16 normalized n)
__device__ float g_s1[B_SZ];
__device__ float g_S2[B_SZ];
__device__ float g_loss;

// ---------------------------------------------------------------------------
#define CP_ASYNC16(dst, src) \
    asm volatile("cp.async.cg.shared.global [%0], [%1], 16;" :: "r"(dst), "l"(src) : "memory")
#define CP_COMMIT() asm volatile("cp.async.commit_group;" ::: "memory")
#define CP_WAIT1()  asm volatile("cp.async.wait_group 1;" ::: "memory")
#define CP_WAIT0()  asm volatile("cp.async.wait_group 0;" ::: "memory")

__device__ __forceinline__ uint32_t smem_u32(const void* p) {
    uint32_t a;
    asm("{ .reg .u64 t; cvta.to.shared.u64 t, %1; cvt.u32.u64 %0, t; }"
        : "=r"(a) : "l"(p));
    return a;
}

// ---------------------------------------------------------------------------
// Kernel 1 (fused prep): blocks [0, B_SZ) handle q/p rows (qhat, s1, S2=0,
// loss=0); blocks [B_SZ, B_SZ+N_SZ) handle negative rows (nhat).
// Inputs are read once -> __ldcs streaming loads keep them out of L2's way.
// ---------------------------------------------------------------------------
__global__ __launch_bounds__(256) void prep_fused_kernel(const float* __restrict__ q,
                                                         const float* __restrict__ p,
                                                         const float* __restrict__ nkeys) {
    const int t = threadIdx.x;
    const int wid = t >> 5, lane = t & 31;

    if (blockIdx.x < B_SZ) {
        const int b = blockIdx.x;
        const float4* q4 = (const float4*)(q + (size_t)b * D_SZ);
        const float4* p4 = (const float4*)(p + (size_t)b * D_SZ);

        float4 a = __ldcs(q4 + t);
        float4 c = __ldcs(p4 + t);
        float qq = a.x * a.x + a.y * a.y + a.z * a.z + a.w * a.w;
        float pp = c.x * c.x + c.y * c.y + c.z * c.z + c.w * c.w;
        float qp = a.x * c.x + a.y * c.y + a.z * c.z + a.w * c.w;

        #pragma unroll
        for (int off = 16; off > 0; off >>= 1) {
            qq += __shfl_xor_sync(0xffffffff, qq, off);
            pp += __shfl_xor_sync(0xffffffff, pp, off);
            qp += __shfl_xor_sync(0xffffffff, qp, off);
        }
        __shared__ float sq[8], sp[8], sqp[8], s_rq;
        if (lane == 0) { sq[wid] = qq; sp[wid] = pp; sqp[wid] = qp; }
        __syncthreads();
        if (t == 0) {
            float tq = 0.f, tp = 0.f, tqp = 0.f;
            #pragma unroll
            for (int i = 0; i < 8; i++) { tq += sq[i]; tp += sp[i]; tqp += sqp[i]; }
            float qn = sqrtf(tq), pn = sqrtf(tp);
            float pos = tqp / fmaxf(qn * pn, EPS_F);
            g_s1[b] = __expf(pos * INV_T);
            g_S2[b] = 0.0f;
            if (b == 0) g_loss = 0.0f;
            s_rq = (qn > 0.f) ? (1.0f / qn) : 0.0f;
        }
        __syncthreads();
        const float rq = s_rq;
        __half* out = g_qhat + (size_t)b * D_SZ + t * 4;
        out[0] = __float2half(a.x * rq);
        out[1] = __float2half(a.y * rq);
        out[2] = __float2half(a.z * rq);
        out[3] = __float2half(a.w * rq);
    } else {
        const int nrow = blockIdx.x - B_SZ;
        const float4* n4 = (const float4*)(nkeys + (size_t)nrow * D_SZ);
        float4 a = __ldcs(n4 + t);
        float nn = a.x * a.x + a.y * a.y + a.z * a.z + a.w * a.w;
        #pragma unroll
        for (int off = 16; off > 0; off >>= 1)
            nn += __shfl_xor_sync(0xffffffff, nn, off);
        __shared__ float sn[8], s_rn;
        if (lane == 0) sn[wid] = nn;
        __syncthreads();
        if (t == 0) {
            float tn = 0.f;
            #pragma unroll
            for (int i = 0; i < 8; i++) tn += sn[i];
            float norm = sqrtf(tn);
            s_rn = (norm > 0.f) ? (1.0f / norm) : 0.0f;
        }
        __syncthreads();
        const float rn = s_rn;
        __half* out = g_nhat + (size_t)nrow * D_SZ + t * 4;
        out[0] = __float2half(a.x * rn);
        out[1] = __float2half(a.y * rn);
        out[2] = __float2half(a.z * rn);
        out[3] = __float2half(a.w * rn);
    }
}

// ---------------------------------------------------------------------------
// Kernel 2: wmma GEMM (fp16 in, fp16 acc) + fused exp/rowsum. R11 verbatim:
//   Block 128x256, 256 threads (8 warps, 2x4), warp tile 64x64, KC=64,
//   2-stage cp.async, 2 CTAs/SM, full kk unroll, two barriers per chunk.
// ---------------------------------------------------------------------------
#define BM 128
#define BN 256
#define KC 64
#define CHUNKS (D_SZ / KC)        // 16
#define KP 72                     // smem row pitch in fp16 elems (144B)
#define A_ST (BM * KP)            // 9216 elems
#define B_ST (BN * KP)            // 18432 elems
#define STAGE_ELEMS (A_ST + B_ST) // 27648 elems = 55296 B
#define SMEM_BYTES (2 * STAGE_ELEMS * 2)   // 110592
#define CPH 24                    // epilogue scratch pitch (halves)

__global__ __launch_bounds__(256, 2) void gemm_exp_kernel() {
    extern __shared__ __half sm[];
    const int tid = threadIdx.x;
    const int wid = tid >> 5, lane = tid & 31;
    const int wm = wid >> 2;          // 0..1 -> 64-row strip
    const int wn = wid & 3;           // 0..3 -> 64-col strip
    const int m0 = blockIdx.y * BM;
    const int n0 = blockIdx.x * BN;
    const uint32_t sbase = smem_u32(sm);

    uint32_t a_off[4], b_off[8];
    const __half* a_src[4];
    const __half* b_src[8];
    #pragma unroll
    for (int i = 0; i < 4; i++) {
        int idx = tid + i * 256;
        int row = idx >> 3, seg = idx & 7;
        a_off[i] = (uint32_t)(row * KP + seg * 8) * 2;
        a_src[i] = g_qhat + (size_t)(m0 + row) * D_SZ + seg * 8;
    }
    #pragma unroll
    for (int i = 0; i < 8; i++) {
        int idx = tid + i * 256;
        int row = idx >> 3, seg = idx & 7;
        b_off[i] = (uint32_t)(A_ST + row * KP + seg * 8) * 2;
        b_src[i] = g_nhat + (size_t)(n0 + row) * D_SZ + seg * 8;
    }

    wmma::fragment<wmma::accumulator, 16, 16, 16, __half> acc[4][4];
    #pragma unroll
    for (int mf = 0; mf < 4; mf++)
        #pragma unroll
        for (int nf = 0; nf < 4; nf++)
            wmma::fill_fragment(acc[mf][nf], __float2half(0.0f));

    // Prologue: chunk 0 into slot 0
    {
        #pragma unroll
        for (int i = 0; i < 4; i++) CP_ASYNC16(sbase + a_off[i], a_src[i]);
        #pragma unroll
        for (int i = 0; i < 8; i++) CP_ASYNC16(sbase + b_off[i], b_src[i]);
        CP_COMMIT();
    }

    for (int kt = 0; kt < CHUNKS; kt++) {
        if (kt + 1 < CHUNKS) {
            uint32_t st = sbase + ((kt + 1) & 1) * (STAGE_ELEMS * 2);
            int k0 = (kt + 1) * KC;
            #pragma unroll
            for (int i = 0; i < 4; i++) CP_ASYNC16(st + a_off[i], a_src[i] + k0);
            #pragma unroll
            for (int i = 0; i < 8; i++) CP_ASYNC16(st + b_off[i], b_src[i] + k0);
            CP_COMMIT();
            CP_WAIT1();
        } else {
            CP_WAIT0();
        }
        __syncthreads();   // chunk kt visible to all warps

        const __half* As = sm + (kt & 1) * STAGE_ELEMS;
        const __half* Bs = As + A_ST;
        #pragma unroll
        for (int kk = 0; kk < 4; kk++) {
            wmma::fragment<wmma::matrix_a, 16, 16, 16, __half, wmma::row_major> af[4];
            #pragma unroll
            for (int mf = 0; mf < 4; mf++)
                wmma::load_matrix_sync(af[mf], As + (wm * 64 + mf * 16) * KP + kk * 16, KP);
            #pragma unroll
            for (int nf = 0; nf < 4; nf++) {
                wmma::fragment<wmma::matrix_b, 16, 16, 16, __half, wmma::col_major> bf;
                wmma::load_matrix_sync(bf, Bs + (wn * 64 + nf * 16) * KP + kk * 16, KP);
                #pragma unroll
                for (int mf = 0; mf < 4; mf++)
                    wmma::mma_sync(acc[mf][nf], af[mf], bf, acc[mf][nf]);
            }
        }
        __syncthreads();   // protect slot (kt&1) before refill at kt+2
    }

    // Epilogue: half accs -> scratch -> exp(fp32) -> rowsum.
    __half* scratch = sm + wid * (16 * CPH);
    #pragma unroll
    for (int mf = 0; mf < 4; mf++) {
        float partial = 0.0f;
        #pragma unroll
        for (int nf = 0; nf < 4; nf++) {
            wmma::store_matrix_sync(scratch, acc[mf][nf], CPH, wmma::mem_row_major);
            __syncwarp();
            const int r = lane & 15, h = lane >> 4;
            const __half* pr = scratch + r * CPH + h * 8;
            #pragma unroll
            for (int c = 0; c < 8; c++)
                partial += __expf(__half2float(pr[c]) * INV_T);
            __syncwarp();
        }
        partial += __shfl_xor_sync(0xffffffff, partial, 16);
        if (lane < 16)
            atomicAdd(&g_S2[m0 + wm * 64 + mf * 16 + lane], partial);
    }
}

// ---------------------------------------------------------------------------
// Kernel 3/4: per-row loss terms -> g_loss; write out.
// ---------------------------------------------------------------------------
__global__ __launch_bounds__(256) void finalize_partial_kernel() {
    const int b = blockIdx.x * 256 + threadIdx.x;
    float s1 = g_s1[b];
    float s2 = g_S2[b] * (1.0f / (float)N_SZ);
    float v = -logf(s1 / (s1 + s2));

    __shared__ float sd[256];
    sd[threadIdx.x] = v;
    __syncthreads();
    #pragma unroll
    for (int stride = 128; stride > 0; stride >>= 1) {
        if (threadIdx.x < stride) sd[threadIdx.x] += sd[threadIdx.x + stride];
        __syncthreads();
    }
    if (threadIdx.x == 0) atomicAdd(&g_loss, sd[0]);
}

__global__ void finalize_write_kernel(float* __restrict__ out) {
    out[0] = g_loss * (1.0f / (float)B_SZ);
}

// ---------------------------------------------------------------------------
extern "C" void kernel_launch(void* const* d_in, const int* in_sizes, int n_in,
                              void* d_out, int out_size) {
    const float* q  = (const float*)d_in[0];
    const float* p  = (const float*)d_in[1];
    const float* nk = (const float*)d_in[2];
    float* out = (float*)d_out;

    cudaFuncSetAttribute(gemm_exp_kernel,
                         cudaFuncAttributeMaxDynamicSharedMemorySize, SMEM_BYTES);

    prep_fused_kernel<<<B_SZ + N_SZ, 256>>>(q, p, nk);
    gemm_exp_kernel<<<dim3(N_SZ / BN, B_SZ / BM), 256, SMEM_BYTES>>>();
    finalize_partial_kernel<<<B_SZ / 256, 256>>>();
    finalize_write_kernel<<<1, 1>>>(out);
}